// round 14
// baseline (speedup 1.0000x reference)
#include <cuda_runtime.h>
#include <cstdint>

// SpatialCorrelationSampler via warp-level mma.sync fp16 m16n8k16 (fp32 acc).
// Round 14: persistent blocks (296 = 2/SM, fully resident), continuous
// 3-stage cp.async ring that streams across tile boundaries (no drain),
// epilogue scratch disjoint from stages. Math identical to round 13.
//
// Per tile: 8x8 px (M=64), halo 16x16 (N=256), K=256, band-skip GEMM.

namespace {

constexpr int C = 256, H = 128, W = 128, PATCH = 9, PAD = 4;
constexpr int HW = H * W, CHW = C * HW;
constexpr int CCH = 16, NCHUNK = 16;
constexpr int CHBYTES = CCH * HW * 4;

constexpr int A_ST = 76, B_ST = 268;              // round-13 conflict-free pads
constexpr int A_STAGE = CCH * A_ST * 4;           // 4864
constexpr int B_STAGE = CCH * B_ST * 4;           // 17152
constexpr int STAGE = A_STAGE + B_STAGE;          // 22016 (floats/32: aligned)
constexpr int STAGES = 3;
constexpr int D_OFF = STAGES * STAGE;             // 66048
constexpr int D_ST = 162;                         // banded D row (160+2), even
constexpr int DYN_BYTES = D_OFF + 64 * D_ST * 4;  // 107520 -> 2 blocks/SM

constexpr int NBLK = 296, NTILE = 1024;

__device__ __forceinline__ void cp16(uint32_t dst, const void* src, uint32_t sz) {
    asm volatile("cp.async.cg.shared.global [%0], [%1], 16, %2;"
                 :: "r"(dst), "l"(src), "r"(sz));
}
__device__ __forceinline__ void cp_commit() {
    asm volatile("cp.async.commit_group;" ::: "memory");
}
__device__ __forceinline__ void cp_wait1() {
    asm volatile("cp.async.wait_group 1;" ::: "memory");
}
__device__ __forceinline__ uint32_t pkh(float v_even, float v_odd) {
    uint32_t r;
    asm("cvt.rn.f16x2.f32 %0, %1, %2;" : "=r"(r) : "f"(v_odd), "f"(v_even));
    return r;
}
__device__ __forceinline__ void mma_fp16(float* d, const uint32_t* a,
                                         uint32_t b0, uint32_t b1) {
    asm volatile("mma.sync.aligned.m16n8k16.row.col.f32.f16.f16.f32 "
                 "{%0,%1,%2,%3}, {%4,%5,%6,%7}, {%8,%9}, {%0,%1,%2,%3};"
                 : "+f"(d[0]), "+f"(d[1]), "+f"(d[2]), "+f"(d[3])
                 : "r"(a[0]), "r"(a[1]), "r"(a[2]), "r"(a[3]), "r"(b0), "r"(b1));
}

__global__ __launch_bounds__(256, 2)
void corr_fp16p_kernel(const float* __restrict__ in1,
                       const float* __restrict__ in2,
                       float* __restrict__ out) {
    extern __shared__ char sm[];
    const uint32_t smb = (uint32_t)__cvta_generic_to_shared(sm);
    const int tid  = threadIdx.x;
    const int warp = tid >> 5;
    const int lane = tid & 31;

    // ---------- tile-independent copy-slot geometry -------------------------
    // slots 0..255: A [k(16)][p(64)]; 256..1279: B [k(16)][q(256)]
    uint32_t smoff[5];
    int off[5];                       // float offset from tile origin
#pragma unroll
    for (int i = 0; i < 5; ++i) {
        int s = tid + i * 256;
        if (s < 256) {                               // A slot
            int kk = s >> 4, j = s & 15;
            smoff[i] = (uint32_t)((kk * A_ST + j * 4) * 4);
            off[i] = kk * HW + (j >> 1) * W + (j & 1) * 4;
        } else {                                     // B slots
            int u = s - 256;
            int kk = u >> 6, j = u & 63;
            smoff[i] = (uint32_t)(A_STAGE + (kk * B_ST + j * 4) * 4);
            off[i] = kk * HW + ((j >> 2) - PAD) * W + ((j & 3) * 4 - PAD);
        }
    }
    // validity mask (bit i) for a tile at (h0, w0); A always valid
    auto calc_mask = [&](int h0, int w0) -> uint32_t {
        uint32_t m = 1u;
#pragma unroll
        for (int i = 1; i < 5; ++i) {
            int j  = (tid + i * 256 - 256) & 63;
            int gy = h0 + (j >> 2) - PAD;
            int gx = w0 + (j & 3) * 4 - PAD;
            if (gy >= 0 && gy < H && gx >= 0 && gx + 4 <= W) m |= (1u << i);
        }
        return m;
    };
    auto issue = [&](int orig, uint32_t mask, int k, int st) {
        uint32_t sbase = smb + (uint32_t)(st * STAGE);
        size_t coff = (size_t)k * CHBYTES;
#pragma unroll
        for (int i = 0; i < 5; ++i) {
            bool v = (mask >> i) & 1;
            int o = v ? (orig + off[i]) : 0;         // 0 -> valid addr, sz 0
            const char* base = (i == 0) ? (const char*)in1 : (const char*)in2;
            cp16(sbase + smoff[i], base + (size_t)o * 4 + coff, v ? 16u : 0u);
        }
        cp_commit();
    };

    // ---------- MMA roles (round-13 validated) ------------------------------
    const int g = lane >> 2, tq = lane & 3;
    const int mt   = warp >> 1;
    const int half = warp & 1;
    const int qr0  = 2 * mt + 5 * half;
    float* Dm = (float*)(sm + D_OFF);

    float acc[10][4];
#pragma unroll
    for (int j = 0; j < 10; ++j)
#pragma unroll
        for (int q = 0; q < 4; ++q) acc[j][q] = 0.f;

    // ---------- first tile + prologue ---------------------------------------
    int t  = blockIdx.x;
    int h0 = ((t & 255) >> 4) * 8, w0 = (t & 15) * 8;
    int origC = (t >> 8) * CHW + h0 * W + w0;
    uint32_t maskC = calc_mask(h0, w0);

    issue(origC, maskC, 0, 0);
    issue(origC, maskC, 1, 1);
    int stage = 0;   // stage of the chunk about to be consumed

    for (;;) {
        // next-tile params (prefetched chunks spill into next tile)
        const int tn = t + NBLK;
        const bool hasNext = (tn < NTILE);
        int origN = 0, h0n = 0, w0n = 0;
        uint32_t maskN = 0;
        if (hasNext) {
            h0n = ((tn & 255) >> 4) * 8;
            w0n = (tn & 15) * 8;
            origN = (tn >> 8) * CHW + h0n * W + w0n;
            maskN = calc_mask(h0n, w0n);
        }

#pragma unroll 1
        for (int k = 0; k < NCHUNK; ++k) {
            cp_wait1();        // pending = {cg, cg+1} -> chunk cg complete
            __syncthreads();   // visible; stage (cg+2)%3 fully read at cg-1

            int ist = stage + 2; if (ist >= STAGES) ist -= STAGES;
            if (k + 2 < NCHUNK)      issue(origC, maskC, k + 2, ist);
            else if (hasNext)        issue(origN, maskN, k + 2 - NCHUNK, ist);
            else                     cp_commit();   // uniform accounting

            const float* A  = (const float*)(sm + stage * STAGE);
            const float* Bs = (const float*)(sm + stage * STAGE + A_STAGE);

            const int p = mt * 16 + g;
            uint32_t a[4];
            a[0] = pkh(A[(2 * tq) * A_ST + p],         A[(2 * tq + 1) * A_ST + p]);
            a[1] = pkh(A[(2 * tq) * A_ST + p + 8],     A[(2 * tq + 1) * A_ST + p + 8]);
            a[2] = pkh(A[(2 * tq + 8) * A_ST + p],     A[(2 * tq + 9) * A_ST + p]);
            a[3] = pkh(A[(2 * tq + 8) * A_ST + p + 8], A[(2 * tq + 9) * A_ST + p + 8]);

#pragma unroll
            for (int j = 0; j < 10; ++j) {
                const int q = (qr0 + (j >> 1)) * 16 + (j & 1) * 8 + g;
                uint32_t b0 = pkh(Bs[(2 * tq) * B_ST + q],
                                  Bs[(2 * tq + 1) * B_ST + q]);
                uint32_t b1 = pkh(Bs[(2 * tq + 8) * B_ST + q],
                                  Bs[(2 * tq + 9) * B_ST + q]);
                mma_fp16(acc[j], a, b0, b1);
            }
            stage = (stage + 1 == STAGES) ? 0 : stage + 1;
        }

        // ---------- per-tile epilogue (D region disjoint from stages) -------
        {
            const int c2 = tq * 2, px = mt * 16 + g;
#pragma unroll
            for (int j = 0; j < 10; ++j) {
                const int lr = half * 5 + (j >> 1);
                const int q  = lr * 16 + (j & 1) * 8 + c2;
                *(float2*)&Dm[px * D_ST + q]       = make_float2(acc[j][0], acc[j][1]);
                *(float2*)&Dm[(px + 8) * D_ST + q] = make_float2(acc[j][2], acc[j][3]);
                acc[j][0] = acc[j][1] = acc[j][2] = acc[j][3] = 0.f;
            }
        }
        __syncthreads();

        const int bb = t >> 8;
        for (int i2 = tid; i2 < 8 * 81; i2 += 256) {
            const int hp = i2 & 7, dd = i2 >> 3;     // dd = dy*9+dx
            const int dy = dd / 9, dx = dd % 9;
            const int lr = (hp & 1) + dy;            // band-local q-row
            float v[8];
#pragma unroll
            for (int wp = 0; wp < 8; ++wp)
                v[wp] = Dm[(hp * 8 + wp) * D_ST + lr * 16 + wp + dx];
            float* op = out + (((size_t)bb * (PATCH * PATCH) + dd) * H
                               + (h0 + hp)) * W + w0;
            *(float4*)(op)     = make_float4(v[0], v[1], v[2], v[3]);
            *(float4*)(op + 4) = make_float4(v[4], v[5], v[6], v[7]);
        }

        if (!hasNext) break;
        t = tn; h0 = h0n; w0 = w0n; origC = origN; maskC = maskN;
        // no extra sync: Dm isn't rewritten until next epilogue, which is
        // separated from these reads by the 16 chunk-loop barriers.
    }
}

}  // namespace

extern "C" void kernel_launch(void* const* d_in, const int* in_sizes, int n_in,
                              void* d_out, int out_size) {
    const float* in1 = (const float*)d_in[0];
    const float* in2 = (const float*)d_in[1];
    float* out = (float*)d_out;

    cudaFuncSetAttribute(corr_fp16p_kernel,
                         cudaFuncAttributeMaxDynamicSharedMemorySize,
                         DYN_BYTES);

    corr_fp16p_kernel<<<NBLK, 256, DYN_BYTES>>>(in1, in2, out);
}

// round 15
// speedup vs baseline: 1.0686x; 1.0686x over previous
#include <cuda_runtime.h>
#include <cstdint>

// SpatialCorrelationSampler via warp-level mma.sync fp16 m16n8k16 (fp32 acc).
// Round 15: round-13 math (validated, 86.4us) + 3-stage ring + banded-D
// epilogue (both validated in round 14) + __launch_bounds__(256,3):
// 66KB smem/block and <=85 regs -> 3 blocks/SM (6 warps/SMSP) to close the
// exposed-latency gap diagnosed in rounds 13/14.
//
// Per block: tile 8x8 px (M=64), halo 16x16 (N=256), K=256, band-skip GEMM.

namespace {

constexpr int C = 256, H = 128, W = 128, PATCH = 9, PAD = 4;
constexpr int HW = H * W;
constexpr int TW = 8, TH = 8;
constexpr int CCH = 16, NCHUNK = C / CCH;         // 16 chunks, 1 k16 step each
constexpr int CHBYTES = CCH * HW * 4;

constexpr int A_ST = 76, B_ST = 268;              // conflict-free pads (r13)
constexpr int A_STAGE = CCH * A_ST * 4;           // 4864
constexpr int B_STAGE = CCH * B_ST * 4;           // 17152
constexpr int STAGE  = A_STAGE + B_STAGE;         // 22016
constexpr int STAGES = 3;
constexpr int D_ST = 162;                         // banded D stride (160+2), even
constexpr int EPI_BYTES = 64 * D_ST * 4;          // 41472
constexpr int DYN_BYTES = STAGES * STAGE;         // 66048 > EPI_BYTES

constexpr int SLOTS = 5;    // (256 A + 1024 B) float4 per chunk / 256 threads

// ---------------- PTX wrappers (baseline ISA) ------------------------------
__device__ __forceinline__ void cp16(uint32_t dst, const void* src, uint32_t sz) {
    asm volatile("cp.async.cg.shared.global [%0], [%1], 16, %2;"
                 :: "r"(dst), "l"(src), "r"(sz));
}
__device__ __forceinline__ void cp_commit() {
    asm volatile("cp.async.commit_group;" ::: "memory");
}
__device__ __forceinline__ void cp_wait1() {
    asm volatile("cp.async.wait_group 1;" ::: "memory");
}
// pack two fp32 -> fp16x2; v_even lands in the LOWER half (r12-validated)
__device__ __forceinline__ uint32_t pkh(float v_even, float v_odd) {
    uint32_t r;
    asm("cvt.rn.f16x2.f32 %0, %1, %2;" : "=r"(r) : "f"(v_odd), "f"(v_even));
    return r;
}
__device__ __forceinline__ void mma_fp16(float* d, const uint32_t* a,
                                         uint32_t b0, uint32_t b1) {
    asm volatile("mma.sync.aligned.m16n8k16.row.col.f32.f16.f16.f32 "
                 "{%0,%1,%2,%3}, {%4,%5,%6,%7}, {%8,%9}, {%0,%1,%2,%3};"
                 : "+f"(d[0]), "+f"(d[1]), "+f"(d[2]), "+f"(d[3])
                 : "r"(a[0]), "r"(a[1]), "r"(a[2]), "r"(a[3]), "r"(b0), "r"(b1));
}

__global__ __launch_bounds__(256, 3)
void corr_fp16c_kernel(const float* __restrict__ in1,
                       const float* __restrict__ in2,
                       float* __restrict__ out) {
    extern __shared__ char sm[];
    const uint32_t smb = (uint32_t)__cvta_generic_to_shared(sm);

    const int tid  = threadIdx.x;
    const int warp = tid >> 5;
    const int lane = tid & 31;
    const int b  = blockIdx.z;
    const int w0 = blockIdx.x * TW;
    const int h0 = blockIdx.y * TH;

    // ------------- cp.async slot precompute (5 x 16B per thread) -----------
    // slots 0..255: A [k(16)][p(64)];  256..1279: B [k(16)][q(256)]
    uint32_t smoff[SLOTS], gb[SLOTS], sz[SLOTS];
#pragma unroll
    for (int i = 0; i < SLOTS; ++i) {
        int s = tid + i * 256;
        if (s < 256) {                        // A (i = 0)
            int kk = s >> 4, j = s & 15;
            int py = j >> 1, px = (j & 1) * 4;
            smoff[i] = (uint32_t)((kk * A_ST + j * 4) * 4);
            gb[i] = (uint32_t)((((b * C + kk) * H + h0 + py) * W + w0 + px) * 4);
            sz[i] = 16;
        } else {                              // B (i = 1..4)
            int u = s - 256;
            int kk = u >> 6, j = u & 63;
            int hy = j >> 2;
            int gy = h0 + hy - PAD;
            int gx = w0 + (j & 3) * 4 - PAD;  // 16B aligned, all-in or all-out
            bool ok = (gy >= 0 && gy < H && gx >= 0 && gx + 4 <= W);
            smoff[i] = (uint32_t)(A_STAGE + (kk * B_ST + j * 4) * 4);
            gb[i] = ok ? (uint32_t)((((b * C + kk) * H + gy) * W + gx) * 4) : 0u;
            sz[i] = ok ? 16u : 0u;
        }
    }

    auto issue = [&](int ch) {
        if (ch < NCHUNK) {
            int st = ch % STAGES;
            uint32_t sbase = smb + (uint32_t)(st * STAGE);
            size_t coff = (size_t)ch * CHBYTES;
#pragma unroll
            for (int i = 0; i < SLOTS; ++i) {
                const char* base = (i == 0) ? (const char*)in1 : (const char*)in2;
                cp16(sbase + smoff[i], base + coff + gb[i], sz[i]);
            }
        }
        cp_commit();   // uniform group accounting (empty groups at the tail)
    };

    issue(0); issue(1);

    // ------------- MMA roles: warp = (mt, half) ----------------------------
    const int g = lane >> 2, t = lane & 3;
    const int mt   = warp >> 1;            // m16 tile: px [mt*16, +16)
    const int half = warp & 1;
    const int qr0  = 2 * mt + 5 * half;    // first of 5 owned halo rows

    float acc[10][4];                      // j = (row 0..4)*2 + (n8 col 0..1)
#pragma unroll
    for (int j = 0; j < 10; ++j)
#pragma unroll
        for (int q = 0; q < 4; ++q) acc[j][q] = 0.f;

#pragma unroll 1
    for (int k = 0; k < NCHUNK; ++k) {
        cp_wait1();        // pending {k, k+1} -> group k complete
        __syncthreads();   // stage k%3 visible; stage (k+2)%3 fully read (k-1)

        issue(k + 2);

        const float* A  = (const float*)(sm + (k % STAGES) * STAGE);
        const float* Bs = (const float*)(sm + (k % STAGES) * STAGE + A_STAGE);

        // A fragment m16 x k16 (validated map): p = m row, k packed pairs
        const int p = mt * 16 + g;
        uint32_t a[4];
        a[0] = pkh(A[(2 * t) * A_ST + p],         A[(2 * t + 1) * A_ST + p]);
        a[1] = pkh(A[(2 * t) * A_ST + p + 8],     A[(2 * t + 1) * A_ST + p + 8]);
        a[2] = pkh(A[(2 * t + 8) * A_ST + p],     A[(2 * t + 9) * A_ST + p]);
        a[3] = pkh(A[(2 * t + 8) * A_ST + p + 8], A[(2 * t + 9) * A_ST + p + 8]);

#pragma unroll
        for (int j = 0; j < 10; ++j) {
            const int q = (qr0 + (j >> 1)) * 16 + (j & 1) * 8 + g;
            uint32_t b0 = pkh(Bs[(2 * t) * B_ST + q],
                              Bs[(2 * t + 1) * B_ST + q]);
            uint32_t b1 = pkh(Bs[(2 * t + 8) * B_ST + q],
                              Bs[(2 * t + 9) * B_ST + q]);
            mma_fp16(acc[j], a, b0, b1);
        }
    }

    // ------------- epilogue: banded D (r14-validated) -----------------------
    __syncthreads();            // all MMA smem reads done; stages are dead
    float* D = (float*)sm;      // [px 0..63][band-local q 0..159] stride 162

    {
        const int c2 = t * 2;
        const int px = mt * 16 + g;
#pragma unroll
        for (int j = 0; j < 10; ++j) {
            const int lr = half * 5 + (j >> 1);          // band-local row
            const int q  = lr * 16 + (j & 1) * 8 + c2;
            *(float2*)&D[px * D_ST + q]       = make_float2(acc[j][0], acc[j][1]);
            *(float2*)&D[(px + 8) * D_ST + q] = make_float2(acc[j][2], acc[j][3]);
        }
    }
    __syncthreads();

    // 648 output rows (81 planes x 8 h-rows) of 8 floats, coalesced
    for (int i = tid; i < TH * PATCH * PATCH; i += 256) {
        const int hp = i & 7, dd = i >> 3;    // dd = dy*9+dx
        const int dy = dd / 9, dx = dd % 9;
        const int lr = (hp & 1) + dy;         // band-local q-row for pixel row hp
        float v[8];
#pragma unroll
        for (int wp = 0; wp < 8; ++wp)
            v[wp] = D[(hp * 8 + wp) * D_ST + lr * 16 + wp + dx];
        float* op = out + (((size_t)b * (PATCH * PATCH) + dd) * H + (h0 + hp)) * W + w0;
        *(float4*)(op)     = make_float4(v[0], v[1], v[2], v[3]);
        *(float4*)(op + 4) = make_float4(v[4], v[5], v[6], v[7]);
    }
}

}  // namespace

extern "C" void kernel_launch(void* const* d_in, const int* in_sizes, int n_in,
                              void* d_out, int out_size) {
    const float* in1 = (const float*)d_in[0];
    const float* in2 = (const float*)d_in[1];
    float* out = (float*)d_out;

    cudaFuncSetAttribute(corr_fp16c_kernel,
                         cudaFuncAttributeMaxDynamicSharedMemorySize,
                         DYN_BYTES);

    int B = in_sizes[0] / (C * H * W);              // 4
    dim3 grid(W / TW, H / TH, B);                   // (16, 16, 4) = 1024
    corr_fp16c_kernel<<<grid, 256, DYN_BYTES>>>(in1, in2, out);
}